// round 15
// baseline (speedup 1.0000x reference)
#include <cuda_runtime.h>
#include <cstdint>

#define NN 40000
#define EE 640000

__device__ __align__(16) float g_h[(size_t)NN * 160];
__device__ __align__(16) float g_agg[(size_t)NN * 480];
__device__ __align__(16) float g_gates[(size_t)NN * 32];

static constexpr float INV8        = 0.125f;
static constexpr float INV_SQRT32  = 0.17677669529663687f;
static constexpr float INV_SQRT3   = 0.57735026918962576f;
static constexpr float INV_SQRT2   = 0.70710678118654752f;
static constexpr float INV_SQRT96  = 0.10206207261596575f;
static constexpr float INV_SQRT128 = 0.08838834764831845f;
static constexpr float INV_NN      = 0.25f;

__device__ __forceinline__ float sigmoidf_(float x) { return 1.f / (1.f + __expf(-x)); }
__device__ __forceinline__ float siluf_(float x)    { return x / (1.f + __expf(-x)); }

#define GBAR(id) asm volatile("bar.sync %0, 512;" :: "r"(id) : "memory")

__global__ void dummy_kernel() {}

// ---------------- node pre (2 CTAs/SM) + fused g_agg zeroing ----------------
__global__ void __launch_bounds__(640, 2) node_pre_kernel(
    const float* __restrict__ nf, const float* __restrict__ na,
    const float* __restrict__ lin1_ws, const float* __restrict__ lin1_wv)
{
    __shared__ float ws[64 * 64];
    __shared__ float wv[32 * 32];
    __shared__ float sv[32 * 160];
    __shared__ float aa[32];
    int t = threadIdx.x;

    // fused zero of g_agg (overlaps with weight staging + GEMM work below)
    {
        size_t gt = (size_t)blockIdx.x * 640 + t;
        size_t stride = (size_t)gridDim.x * 640;
        float4* p = reinterpret_cast<float4*>(g_agg);
        for (size_t i = gt; i < (size_t)NN * 120; i += stride)
            p[i] = make_float4(0.f, 0.f, 0.f, 0.f);
    }

    for (int i = t; i < 4096; i += 640) ws[i] = lin1_ws[i];
    for (int i = t; i < 1024; i += 640) wv[i] = lin1_wv[i];
    int u = t % 160, q = t / 160;

    for (int chunk = blockIdx.x; chunk < NN / 32; chunk += gridDim.x) {
        int nbase = chunk * 32;
        __syncthreads();
        for (int i = t; i < 32 * 160; i += 640) sv[i] = nf[(size_t)nbase * 160 + i];
        if (t < 32) aa[t] = na[nbase + t];
        __syncthreads();

        if (u < 64) {
            float acc[8];
            #pragma unroll
            for (int k = 0; k < 8; k++) acc[k] = 0.f;
            #pragma unroll
            for (int c = 0; c < 64; c++) {
                float w = ws[c * 64 + u];
                #pragma unroll
                for (int k = 0; k < 8; k++) acc[k] = fmaf(sv[(q * 8 + k) * 160 + c], w, acc[k]);
            }
            #pragma unroll
            for (int k = 0; k < 8; k++) {
                int n = q * 8 + k;
                g_h[(size_t)(nbase + n) * 160 + u] = acc[k] * aa[n] * INV8;
            }
        } else {
            int g = u - 64, d = g / 3, ii = g - d * 3;
            float acc[8];
            #pragma unroll
            for (int k = 0; k < 8; k++) acc[k] = 0.f;
            #pragma unroll
            for (int c = 0; c < 32; c++) {
                float w = wv[c * 32 + d];
                #pragma unroll
                for (int k = 0; k < 8; k++) acc[k] = fmaf(sv[(q * 8 + k) * 160 + 64 + c * 3 + ii], w, acc[k]);
            }
            #pragma unroll
            for (int k = 0; k < 8; k++) {
                int n = q * 8 + k;
                g_h[(size_t)(nbase + n) * 160 + u] = acc[k] * aa[n] * INV_SQRT32;
            }
        }
    }
}

// ---------------- edge kernel (byte-identical to R12/R14 baseline) ----------------
#define G_ES    0
#define G_HID   4352
#define G_HSV   8704
#define G_EA    19200
#define G_IDX   19456
#define GROUP_FLOATS 19584
#define W_FLOATS 18432
#define ESMEM_FLOATS (W_FLOATS + 2 * GROUP_FLOATS)
#define ESMEM_BYTES  (ESMEM_FLOATS * 4)

__global__ void __launch_bounds__(1024) edge_kernel(
    const float* __restrict__ edge_scalars, const int* __restrict__ edge_src,
    const int* __restrict__ edge_dst, const float* __restrict__ edge_attr,
    const float* __restrict__ fc_w1, const float* __restrict__ fc_w2)
{
    extern __shared__ float sm[];
    float* w1s = sm;
    float* w2s = sm + 4096;

    int t = threadIdx.x;
    for (int i = t; i < 4096;  i += 1024) w1s[i] = fc_w1[i];
    for (int i = t; i < 14336; i += 1024) w2s[i] = fc_w2[i];
    __syncthreads();

    int wid  = t >> 5;
    int lane = t & 31;
    int g    = wid >> 4;
    int gw   = wid & 15;
    int t2   = t & 511;
    int barid = 1 + g;

    float* gb   = sm + W_FLOATS + g * GROUP_FLOATS;
    float* es   = gb + G_ES;
    float* hid  = gb + G_HID;
    float* hsv  = gb + G_HSV;
    float* ea   = gb + G_EA;
    int* src_sm = (int*)(gb + G_IDX);
    int* dst_sm = src_sm + 64;

    int njq = (gw < 8) ? 4 : 3;

    for (int tile = blockIdx.x * 2 + g; tile < EE / 64; tile += 296) {
        int base = tile * 64;
        GBAR(barid);

        #pragma unroll
        for (int m = 0; m < 2; m++) {
            int idx = t2 + m * 512;
            int e = idx >> 4, c4 = idx & 15;
            float4 v = reinterpret_cast<const float4*>(edge_scalars + (size_t)base * 64)[idx];
            *reinterpret_cast<float4*>(es + e * 68 + c4 * 4) = v;
        }
        if (t2 < 64) {
            src_sm[t2] = edge_src[base + t2];
            dst_sm[t2] = edge_dst[base + t2];
            *reinterpret_cast<float4*>(ea + t2 * 4) =
                reinterpret_cast<const float4*>(edge_attr)[base + t2];
        }
        GBAR(barid);

        #pragma unroll
        for (int m = 0; m < 5; m++) {
            int idx = t2 + m * 512;
            int e = idx / 40, c4 = idx - e * 40;
            float4 v = reinterpret_cast<const float4*>(g_h + (size_t)src_sm[e] * 160)[c4];
            *reinterpret_cast<float4*>(hsv + e * 164 + c4 * 4) = v;
        }
        {
            float a0[4] = {0.f, 0.f, 0.f, 0.f};
            float a1[4] = {0.f, 0.f, 0.f, 0.f};
            #pragma unroll
            for (int cc = 0; cc < 64; cc += 4) {
                float4 x0 = *reinterpret_cast<const float4*>(es + lane * 68 + cc);
                float4 x1 = *reinterpret_cast<const float4*>(es + (lane + 32) * 68 + cc);
                float xa0[4] = {x0.x, x0.y, x0.z, x0.w};
                float xa1[4] = {x1.x, x1.y, x1.z, x1.w};
                #pragma unroll
                for (int k = 0; k < 4; k++) {
                    float4 w = *reinterpret_cast<const float4*>(w1s + (cc + k) * 64 + gw * 4);
                    a0[0] = fmaf(xa0[k], w.x, a0[0]); a0[1] = fmaf(xa0[k], w.y, a0[1]);
                    a0[2] = fmaf(xa0[k], w.z, a0[2]); a0[3] = fmaf(xa0[k], w.w, a0[3]);
                    a1[0] = fmaf(xa1[k], w.x, a1[0]); a1[1] = fmaf(xa1[k], w.y, a1[1]);
                    a1[2] = fmaf(xa1[k], w.z, a1[2]); a1[3] = fmaf(xa1[k], w.w, a1[3]);
                }
            }
            *reinterpret_cast<float4*>(hid + lane * 68 + gw * 4) = make_float4(
                siluf_(a0[0] * INV8), siluf_(a0[1] * INV8), siluf_(a0[2] * INV8), siluf_(a0[3] * INV8));
            *reinterpret_cast<float4*>(hid + (lane + 32) * 68 + gw * 4) = make_float4(
                siluf_(a1[0] * INV8), siluf_(a1[1] * INV8), siluf_(a1[2] * INV8), siluf_(a1[3] * INV8));
        }
        GBAR(barid);

        float acc[4][2][4];
        #pragma unroll
        for (int q = 0; q < 4; q++)
            #pragma unroll
            for (int s = 0; s < 2; s++)
                #pragma unroll
                for (int k = 0; k < 4; k++) acc[q][s][k] = 0.f;

        #pragma unroll
        for (int cc = 0; cc < 64; cc += 4) {
            float4 x0 = *reinterpret_cast<const float4*>(hid + lane * 68 + cc);
            float4 x1 = *reinterpret_cast<const float4*>(hid + (lane + 32) * 68 + cc);
            float xa0[4] = {x0.x, x0.y, x0.z, x0.w};
            float xa1[4] = {x1.x, x1.y, x1.z, x1.w};
            #pragma unroll
            for (int q = 0; q < 4; q++) {
                if (q < njq) {
                    int j = (gw + 16 * q) * 4;
                    #pragma unroll
                    for (int k = 0; k < 4; k++) {
                        float4 w = *reinterpret_cast<const float4*>(w2s + (cc + k) * 224 + j);
                        acc[q][0][0] = fmaf(xa0[k], w.x, acc[q][0][0]);
                        acc[q][0][1] = fmaf(xa0[k], w.y, acc[q][0][1]);
                        acc[q][0][2] = fmaf(xa0[k], w.z, acc[q][0][2]);
                        acc[q][0][3] = fmaf(xa0[k], w.w, acc[q][0][3]);
                        acc[q][1][0] = fmaf(xa1[k], w.x, acc[q][1][0]);
                        acc[q][1][1] = fmaf(xa1[k], w.y, acc[q][1][1]);
                        acc[q][1][2] = fmaf(xa1[k], w.z, acc[q][1][2]);
                        acc[q][1][3] = fmaf(xa1[k], w.w, acc[q][1][3]);
                    }
                }
            }
        }

        #pragma unroll
        for (int s = 0; s < 2; s++) {
            int e = 32 * s + lane;
            float4 eav = *reinterpret_cast<const float4*>(ea + e * 4);
            float e0 = eav.x, b0 = eav.y, b1 = eav.z, b2 = eav.w;
            float* R = g_agg + (size_t)dst_sm[e] * 480;
            const float* H = hsv + e * 164;

            float4 hs = *reinterpret_cast<const float4*>(H + 4 * gw);
            {
                float ax = acc[0][s][0] * INV8, ay = acc[0][s][1] * INV8;
                float az = acc[0][s][2] * INV8, aw = acc[0][s][3] * INV8;
                atomicAdd(reinterpret_cast<float4*>(R + 4 * gw), make_float4(
                    ax * hs.x * e0, ay * hs.y * e0, az * hs.z * e0, aw * hs.w * e0));
            }
            {
                float ax = acc[1][s][0] * INV8, ay = acc[1][s][1] * INV8;
                float az = acc[1][s][2] * INV8, aw = acc[1][s][3] * INV8;
                float c0 = ax * hs.x, c1 = ay * hs.y, c2 = az * hs.z, c3 = aw * hs.w;
                float* o = R + 96 + 12 * gw;
                atomicAdd(reinterpret_cast<float4*>(o),     make_float4(c0*b0, c0*b1, c0*b2, c1*b0));
                atomicAdd(reinterpret_cast<float4*>(o + 4), make_float4(c1*b1, c1*b2, c2*b0, c2*b1));
                atomicAdd(reinterpret_cast<float4*>(o + 8), make_float4(c2*b2, c3*b0, c3*b1, c3*b2));
            }
            if (gw < 8) {
                int hb = 64 + 12 * gw;
                float4 h0 = *reinterpret_cast<const float4*>(H + hb);
                float4 h1 = *reinterpret_cast<const float4*>(H + hb + 4);
                float4 h2 = *reinterpret_cast<const float4*>(H + hb + 8);
                float A[12] = {h0.x, h0.y, h0.z, h0.w, h1.x, h1.y, h1.z, h1.w, h2.x, h2.y, h2.z, h2.w};
                {
                    float ax = acc[2][s][0] * INV8, ay = acc[2][s][1] * INV8;
                    float az = acc[2][s][2] * INV8, aw = acc[2][s][3] * INV8;
                    float* o = R + 288 + 12 * gw;
                    atomicAdd(reinterpret_cast<float4*>(o), make_float4(
                        ax*A[0]*e0, ax*A[1]*e0, ax*A[2]*e0, ay*A[3]*e0));
                    atomicAdd(reinterpret_cast<float4*>(o + 4), make_float4(
                        ay*A[4]*e0, ay*A[5]*e0, az*A[6]*e0, az*A[7]*e0));
                    atomicAdd(reinterpret_cast<float4*>(o + 8), make_float4(
                        az*A[8]*e0, aw*A[9]*e0, aw*A[10]*e0, aw*A[11]*e0));
                }
                {
                    float sc = INV8 * INV_SQRT2;
                    float ax = acc[3][s][0] * sc, ay = acc[3][s][1] * sc;
                    float az = acc[3][s][2] * sc, aw = acc[3][s][3] * sc;
                    float* o = R + 384 + 12 * gw;
                    atomicAdd(reinterpret_cast<float4*>(o), make_float4(
                        ax*(A[1]*b2 - A[2]*b1), ax*(A[2]*b0 - A[0]*b2),
                        ax*(A[0]*b1 - A[1]*b0), ay*(A[4]*b2 - A[5]*b1)));
                    atomicAdd(reinterpret_cast<float4*>(o + 4), make_float4(
                        ay*(A[5]*b0 - A[3]*b2), ay*(A[3]*b1 - A[4]*b0),
                        az*(A[7]*b2 - A[8]*b1), az*(A[8]*b0 - A[6]*b2)));
                    atomicAdd(reinterpret_cast<float4*>(o + 8), make_float4(
                        az*(A[6]*b1 - A[7]*b0), aw*(A[10]*b2 - A[11]*b1),
                        aw*(A[11]*b0 - A[9]*b2), aw*(A[9]*b1 - A[10]*b0)));
                }
            } else {
                int c = 4 * gw - 32;
                int hb = 64 + c * 3;
                float4 h0 = *reinterpret_cast<const float4*>(H + hb);
                float4 h1 = *reinterpret_cast<const float4*>(H + hb + 4);
                float4 h2 = *reinterpret_cast<const float4*>(H + hb + 8);
                float A[12] = {h0.x, h0.y, h0.z, h0.w, h1.x, h1.y, h1.z, h1.w, h2.x, h2.y, h2.z, h2.w};
                float sc = INV8 * INV_SQRT3;
                float ax = acc[2][s][0] * sc, ay = acc[2][s][1] * sc;
                float az = acc[2][s][2] * sc, aw = acc[2][s][3] * sc;
                atomicAdd(reinterpret_cast<float4*>(R + 64 + c), make_float4(
                    ax * (A[0]*b0 + A[1]*b1 + A[2]*b2),
                    ay * (A[3]*b0 + A[4]*b1 + A[5]*b2),
                    az * (A[6]*b0 + A[7]*b1 + A[8]*b2),
                    aw * (A[9]*b0 + A[10]*b1 + A[11]*b2)));
            }
        }
    }
}

// ---------------- node post, split: scalar kernel (2 CTAs/SM) ----------------
#define NPS_FLOATS 25664
#define NPS_BYTES (NPS_FLOATS * 4)
__global__ void __launch_bounds__(768, 2) np_scalar_kernel(
    const float* __restrict__ nf, const float* __restrict__ na,
    const float* __restrict__ sc_ws, const float* __restrict__ lin2_ws,
    float* __restrict__ out)
{
    extern __shared__ float sm[];
    float* scws = sm;             // 6144
    float* l2ws = sm + 6144;      // 9216
    float* svs  = sm + 15360;     // 4096 (64x64)
    float* ags  = sm + 19456;     // 6144 (64x96)
    float* aa   = sm + 25600;     // 64

    int t = threadIdx.x;
    for (int i = t; i < 6144; i += 768) scws[i] = sc_ws[i];
    for (int i = t; i < 9216; i += 768) l2ws[i] = lin2_ws[i];
    int u = t % 96, q = t / 96;

    for (int chunk = blockIdx.x; chunk < NN / 64; chunk += gridDim.x) {
        int nbase = chunk * 64;
        __syncthreads();
        for (int i = t; i < 1024; i += 768) {
            int node = i >> 4, c4 = i & 15;
            *reinterpret_cast<float4*>(svs + node * 64 + c4 * 4) =
                reinterpret_cast<const float4*>(nf + (size_t)(nbase + node) * 160)[c4];
        }
        for (int i = t; i < 1536; i += 768) {
            int node = i / 24, c4 = i % 24;
            *reinterpret_cast<float4*>(ags + node * 96 + c4 * 4) =
                reinterpret_cast<const float4*>(g_agg + (size_t)(nbase + node) * 480)[c4];
        }
        if (t < 64) aa[t] = na[nbase + t];
        __syncthreads();

        float acc[8], ac2[8];
        #pragma unroll
        for (int k = 0; k < 8; k++) { acc[k] = 0.f; ac2[k] = 0.f; }
        #pragma unroll
        for (int c = 0; c < 64; c++) {
            float w = scws[c * 96 + u];
            #pragma unroll
            for (int k = 0; k < 8; k++) acc[k] = fmaf(svs[(q * 8 + k) * 64 + c], w, acc[k]);
        }
        #pragma unroll
        for (int c = 0; c < 96; c++) {
            float w = l2ws[c * 96 + u];
            #pragma unroll
            for (int k = 0; k < 8; k++) ac2[k] = fmaf(ags[(q * 8 + k) * 96 + c], w, ac2[k]);
        }
        #pragma unroll
        for (int k = 0; k < 8; k++) {
            int n = q * 8 + k;
            float pre = (acc[k] * INV8 + ac2[k] * (INV_SQRT96 * INV_NN)) * aa[n];
            if (u < 64) out[(size_t)(nbase + n) * 160 + u] = siluf_(pre);
            else        g_gates[(size_t)(nbase + n) * 32 + (u - 64)] = sigmoidf_(pre);
        }
    }
}

// ---------------- node post, split: vector kernel (2 CTAs/SM) ----------------
#define NPV_FLOATS 21568
#define NPV_BYTES (NPV_FLOATS * 4)
__global__ void __launch_bounds__(768, 2) np_vector_kernel(
    const float* __restrict__ nf, const float* __restrict__ na,
    const float* __restrict__ sc_wv, const float* __restrict__ lin2_wv,
    float* __restrict__ out)
{
    extern __shared__ float sm[];
    float* scwv = sm;             // 1024
    float* l2wv = sm + 1024;      // 4096
    float* svv  = sm + 5120;      // 3072 (32x96)
    float* agv  = sm + 8192;      // 12288 (32x384)
    float* gts  = sm + 20480;     // 1024 (32x32)
    float* aa   = sm + 21504;     // 32

    int t = threadIdx.x;
    for (int i = t; i < 1024; i += 768) scwv[i] = sc_wv[i];
    for (int i = t; i < 4096; i += 768) l2wv[i] = lin2_wv[i];
    int u = t % 96, q = t / 96;
    int d = u / 3, ii = u - d * 3;

    for (int chunk = blockIdx.x; chunk < NN / 32; chunk += gridDim.x) {
        int nbase = chunk * 32;
        __syncthreads();
        if (t < 768) {
            int node = t / 24, c4 = t % 24;
            *reinterpret_cast<float4*>(svv + node * 96 + c4 * 4) =
                reinterpret_cast<const float4*>(nf + (size_t)(nbase + node) * 160 + 64)[c4];
        }
        for (int i = t; i < 3072; i += 768) {
            int node = i / 96, c4 = i % 96;
            *reinterpret_cast<float4*>(agv + node * 384 + c4 * 4) =
                reinterpret_cast<const float4*>(g_agg + (size_t)(nbase + node) * 480 + 96)[c4];
        }
        if (t < 256) {
            int node = t >> 3, c4 = t & 7;
            *reinterpret_cast<float4*>(gts + node * 32 + c4 * 4) =
                reinterpret_cast<const float4*>(g_gates + (size_t)(nbase + node) * 32)[c4];
        }
        if (t < 32) aa[t] = na[nbase + t];
        __syncthreads();

        float acc[4], ac2[4];
        #pragma unroll
        for (int k = 0; k < 4; k++) { acc[k] = 0.f; ac2[k] = 0.f; }
        #pragma unroll
        for (int c = 0; c < 32; c++) {
            float w = scwv[c * 32 + d];
            #pragma unroll
            for (int k = 0; k < 4; k++) acc[k] = fmaf(svv[(q * 4 + k) * 96 + c * 3 + ii], w, acc[k]);
        }
        #pragma unroll
        for (int c = 0; c < 128; c++) {
            float w = l2wv[c * 32 + d];
            #pragma unroll
            for (int k = 0; k < 4; k++) ac2[k] = fmaf(agv[(q * 4 + k) * 384 + c * 3 + ii], w, ac2[k]);
        }
        #pragma unroll
        for (int k = 0; k < 4; k++) {
            int n = q * 4 + k;
            float pv = (acc[k] * INV_SQRT32 + ac2[k] * (INV_SQRT128 * INV_NN)) * aa[n];
            out[(size_t)(nbase + n) * 160 + 64 + u] = gts[n * 32 + d] * pv;
        }
    }
}

// ---------------- launch ----------------
extern "C" void kernel_launch(void* const* d_in, const int* in_sizes, int n_in,
                              void* d_out, int out_size)
{
    const float* nf      = (const float*)d_in[0];
    const float* na      = (const float*)d_in[1];
    const int*   esrc    = (const int*)  d_in[2];
    const int*   edst    = (const int*)  d_in[3];
    const float* eattr   = (const float*)d_in[4];
    const float* escal   = (const float*)d_in[5];
    const float* lin1_ws = (const float*)d_in[6];
    const float* lin1_wv = (const float*)d_in[7];
    const float* fc_w1   = (const float*)d_in[8];
    const float* fc_w2   = (const float*)d_in[9];
    const float* sc_ws   = (const float*)d_in[10];
    const float* sc_wv   = (const float*)d_in[11];
    const float* lin2_ws = (const float*)d_in[12];
    const float* lin2_wv = (const float*)d_in[13];
    float* out = (float*)d_out;

    cudaFuncSetAttribute(edge_kernel,      cudaFuncAttributeMaxDynamicSharedMemorySize, ESMEM_BYTES);
    cudaFuncSetAttribute(np_scalar_kernel, cudaFuncAttributeMaxDynamicSharedMemorySize, NPS_BYTES);
    cudaFuncSetAttribute(np_vector_kernel, cudaFuncAttributeMaxDynamicSharedMemorySize, NPV_BYTES);

    node_pre_kernel<<<296, 640>>>(nf, na, lin1_ws, lin1_wv);   // idx 0 (zero fused)
    dummy_kernel<<<1, 32>>>();                                 // idx 1
    dummy_kernel<<<1, 32>>>();                                 // idx 2 (keep edge at idx 3 for ncu)
    edge_kernel<<<148, 1024, ESMEM_BYTES>>>(escal, esrc, edst, eattr, fc_w1, fc_w2);  // idx 3 <- profiled
    np_scalar_kernel<<<296, 768, NPS_BYTES>>>(nf, na, sc_ws, lin2_ws, out);
    np_vector_kernel<<<296, 768, NPV_BYTES>>>(nf, na, sc_wv, lin2_wv, out);
}